// round 8
// baseline (speedup 1.0000x reference)
#include <cuda_runtime.h>
#include <cuda_bf16.h>

#define NFLAT 238144        // 64*61*61
#define TOTAL4 7620608      // NFLAT*128/4 float4s in D1
#define PREF_BLOCKS 320
#define PREF_CHUNK 11000    // float4 per prefetch block (~56MB total)

// ---------------- scratch (device globals; no allocation) ----------------
__device__ __align__(128) float g_out1p[4 * 4096 * 32];
__device__ __align__(128) float g_r128[128];
__device__ __align__(128) float g_rt[256];
__device__ __align__(128) float g_qt[256];
__device__ __align__(128) float g_st[256];
__device__ __align__(128) float g_d[256];
__device__ __align__(128) float g_ct[256];
__device__ __align__(128) float g_scores[4096];
__device__ __align__(128) float g_smax[32];
__device__ __align__(128) float g_sink[PREF_BLOCKS];
__device__ __align__(128) unsigned g_count;
__device__ __align__(128) unsigned g_sense;

// ---------------- packed fp32x2 helpers ----------------
typedef unsigned long long ull;
__device__ __forceinline__ ull pack2(float lo, float hi) {
    ull r; asm("mov.b64 %0, {%1,%2};" : "=l"(r) : "f"(lo), "f"(hi)); return r;
}
__device__ __forceinline__ void unpack2(ull v, float& lo, float& hi) {
    asm("mov.b64 {%0,%1}, %2;" : "=f"(lo), "=f"(hi) : "l"(v));
}
__device__ __forceinline__ void fma2(ull& d, ull a, ull b) {
    asm("fma.rn.f32x2 %0, %1, %2, %0;" : "+l"(d) : "l"(a), "l"(b));
}

// =========================================================================
// STAGE 1: conv1 (128 blocks) + transpose->out (256 blocks) + D1 prefetch (320)
// =========================================================================
__global__ __launch_bounds__(256) void stage1_kernel(const float* __restrict__ mem,
                                                     const float* __restrict__ K1,
                                                     const float* __restrict__ D1,
                                                     float* __restrict__ out) {
    __shared__ float sm[7360];
    int bid = blockIdx.x;
    int tid = threadIdx.x;

    if (bid < 128) {
        // ---- conv1: SAME 3x3, 256->32. Block = 2 rows x 64 ic. 4px x 4oc/thread.
        float* sIn = sm;            // 2 halves x 32ic x 67
        float* sW  = sm + 4288;     // 3kw x 32ic x 32oc
        int icq  = bid & 3;
        int h0   = (bid >> 2) * 2;
        int half = tid >> 7;
        int t    = tid & 127;
        int pg = t & 15, og = t >> 4;

        ull acc0[4] = {0ull,0ull,0ull,0ull};
        ull acc1[4] = {0ull,0ull,0ull,0ull};

        for (int kh = 0; kh < 3; kh++) {
            for (int ch = 0; ch < 2; ch++) {
                int ic0 = icq * 64 + ch * 32;
                __syncthreads();
                for (int t2 = tid; t2 < 4224; t2 += 256) {
                    int hh = (t2 >= 2112) ? 1 : 0;
                    int lc = t2 - hh * 2112;
                    int ic = lc & 31, c = lc >> 5;
                    int r = h0 + kh - 1 + hh;
                    int col = c - 1;
                    float v = 0.f;
                    if (r >= 0 && r < 64 && col >= 0 && col < 64)
                        v = mem[(r * 64 + col) * 256 + ic0 + ic];
                    sIn[hh * 2144 + ic * 67 + c] = v;
                }
                for (int t2 = tid; t2 < 3072; t2 += 256) {
                    int oc = t2 & 31, ic = (t2 >> 5) & 31, kw = t2 >> 10;
                    sW[t2] = K1[((kh * 3 + kw) * 256 + ic0 + ic) * 32 + oc];
                }
                __syncthreads();
                const float* base = sIn + half * 2144;
#pragma unroll 4
                for (int ic = 0; ic < 32; ic++) {
                    ull xb[6];
#pragma unroll
                    for (int c = 0; c < 6; c++) {
                        float x = base[ic * 67 + pg * 4 + c];
                        xb[c] = pack2(x, x);
                    }
#pragma unroll
                    for (int kw = 0; kw < 3; kw++) {
                        const ull* wp = (const ull*)&sW[(kw * 32 + ic) * 32 + og * 4];
                        ull w0 = wp[0], w1 = wp[1];
#pragma unroll
                        for (int a = 0; a < 4; a++) {
                            fma2(acc0[a], xb[a + kw], w0);
                            fma2(acc1[a], xb[a + kw], w1);
                        }
                    }
                }
            }
        }
        int row = h0 + half;
#pragma unroll
        for (int a = 0; a < 4; a++) {
            float l0, h1, l2, h3;
            unpack2(acc0[a], l0, h1);
            unpack2(acc1[a], l2, h3);
            *(float4*)&g_out1p[icq * 131072 + (row * 64 + pg * 4 + a) * 32 + og * 4] =
                make_float4(l0, h1, l2, h3);
        }
    } else if (bid < 384) {
        // ---- transpose memory -> out[512 + c*4096 + p], 128p x 32c tiles
        int tb = bid - 128;
        if (tb == 0) {
            if (tid < 128) g_r128[tid] = 0.f;
            g_rt[tid] = 0.f; g_qt[tid] = 0.f; g_st[tid] = 0.f;
            g_d[tid] = 0.f;  g_ct[tid] = 0.f;
        }
        float* tile = sm;   // 128 x 33
        int p0 = (tb >> 3) * 128;
        int c0 = (tb & 7) * 32;
        for (int t2 = tid; t2 < 4096; t2 += 256) {
            int p = t2 >> 5, c = t2 & 31;
            tile[p * 33 + c] = mem[(p0 + p) * 256 + c0 + c];
        }
        __syncthreads();
        for (int t2 = tid; t2 < 4096; t2 += 256) {
            int c = t2 >> 7, p = t2 & 127;
            out[512 + (long)(c0 + c) * 4096 + p0 + p] = tile[p * 33 + c];
        }
    } else {
        // ---- D1 prefetch into L2 (result sunk, never read)
        int pb = bid - 384;
        const float4* D1v = (const float4*)D1;
        long start = (long)pb * PREF_CHUNK;
        long end = start + PREF_CHUNK; if (end > TOTAL4) end = TOTAL4;
        float s = 0.f;
        for (long u = start + tid; u < end; u += 256) {
            float4 v = D1v[u];
            s += v.x + v.y + v.z + v.w;
        }
        g_sink[pb] = s;
    }
}

// =========================================================================
// STAGE 2: fused conv2 + 2x2 mean-pool + GEMV into r128. grid (61, 2)
// =========================================================================
__global__ __launch_bounds__(256) void stage2_kernel(const float* __restrict__ K2,
                                                     const float* __restrict__ D1) {
    extern __shared__ float sm2[];
    float* sIn = sm2;            // 4 rows x 32ic x 65 = 8320 (reused as sC[2][32][64])
    float* sW  = sm2 + 8320;     // 9*32*32 = 9216
    float* sp  = sm2 + 17536;    // pooled 32oc x 64 = 2048
    float* red = sm2 + 19584;    // 8 x 128

    int i    = blockIdx.x;       // pooled row 0..60
    int half = blockIdx.y;
    int tid  = threadIdx.x;

    for (int t = tid; t < 8192; t += 256) {
        int ic = t & 31, col = (t >> 5) & 63, rr = t >> 11;
        const float* p = g_out1p + ((i + rr) * 64 + col) * 32 + ic;
        sIn[(rr * 32 + ic) * 65 + col] = p[0] + p[131072] + p[262144] + p[393216];
    }
    for (int t = tid; t < 9216; t += 256) {
        int ocl = t & 31, ic = (t >> 5) & 31, kk = t >> 10;
        sW[t] = K2[(kk * 32 + ic) * 64 + half * 32 + ocl];
    }
    __syncthreads();

    int pxg = tid & 31, ocg = tid >> 5;
    ull acc[2][2][2];
#pragma unroll
    for (int r = 0; r < 2; r++)
#pragma unroll
        for (int a = 0; a < 2; a++)
#pragma unroll
            for (int b = 0; b < 2; b++) acc[r][a][b] = 0ull;

    int px = pxg * 2;
    if (pxg < 31) {
#pragma unroll
        for (int r = 0; r < 2; r++)
            for (int kh = 0; kh < 3; kh++) {
#pragma unroll 4
                for (int ic = 0; ic < 32; ic++) {
                    ull xb[4];
#pragma unroll
                    for (int c = 0; c < 4; c++) {
                        float x = sIn[((r + kh) * 32 + ic) * 65 + px + c];
                        xb[c] = pack2(x, x);
                    }
#pragma unroll
                    for (int kw = 0; kw < 3; kw++) {
                        const ull* wp = (const ull*)&sW[((kh * 3 + kw) * 32 + ic) * 32 + ocg * 4];
                        ull w0 = wp[0], w1 = wp[1];
                        fma2(acc[r][0][0], xb[kw + 0], w0);
                        fma2(acc[r][0][1], xb[kw + 0], w1);
                        fma2(acc[r][1][0], xb[kw + 1], w0);
                        fma2(acc[r][1][1], xb[kw + 1], w1);
                    }
                }
            }
    }
    __syncthreads();
    if (pxg < 31) {
#pragma unroll
        for (int r = 0; r < 2; r++)
#pragma unroll
            for (int b = 0; b < 2; b++) {
                float lo, hi;
                unpack2(acc[r][0][b], lo, hi);
                sIn[(r * 32 + ocg * 4 + b * 2 + 0) * 64 + px + 0] = lo;
                sIn[(r * 32 + ocg * 4 + b * 2 + 1) * 64 + px + 0] = hi;
                unpack2(acc[r][1][b], lo, hi);
                sIn[(r * 32 + ocg * 4 + b * 2 + 0) * 64 + px + 1] = lo;
                sIn[(r * 32 + ocg * 4 + b * 2 + 1) * 64 + px + 1] = hi;
            }
    }
    __syncthreads();
    for (int t = tid; t < 2048; t += 256) {
        int j = t & 63, ocl = t >> 6;
        if (j < 61)
            sp[ocl * 64 + j] = 0.25f * (sIn[ocl * 64 + j] + sIn[ocl * 64 + j + 1] +
                                        sIn[(32 + ocl) * 64 + j] + sIn[(32 + ocl) * 64 + j + 1]);
    }
    __syncthreads();

    int kq = tid & 31, slot = tid >> 5;
    const float4* D1v = (const float4*)D1;
    float4 a4 = make_float4(0.f, 0.f, 0.f, 0.f);
    for (int rr = slot; rr < 1952; rr += 8) {
        int ocl = rr / 61;
        int j = rr - ocl * 61;
        float s = sp[ocl * 64 + j];
        long fg = (long)((half * 32 + ocl) * 3721 + i * 61 + j);
        float4 dv = D1v[fg * 32 + kq];
        a4.x += s * dv.x; a4.y += s * dv.y; a4.z += s * dv.z; a4.w += s * dv.w;
    }
    float* rp = &red[slot * 128 + kq * 4];
    rp[0] = a4.x; rp[1] = a4.y; rp[2] = a4.z; rp[3] = a4.w;
    __syncthreads();
    if (tid < 128) {
        float v = 0.f;
#pragma unroll
        for (int s = 0; s < 8; s++) v += red[s * 128 + tid];
        atomicAdd(&g_r128[tid], v);
    }
}

// =========================================================================
// STAGE 3: persistent tail chain, 64 blocks, sense-reversal grid barrier
// =========================================================================
__device__ __forceinline__ void gbar() {
    __syncthreads();
    if (threadIdx.x == 0) {
        __threadfence();
        unsigned s = *(volatile unsigned*)&g_sense;
        unsigned prev = atomicAdd(&g_count, 1u);
        if (prev == 63u) {
            g_count = 0u;              // reset BEFORE releasing
            __threadfence();
            atomicExch(&g_sense, s + 1u);
        } else {
            while (*(volatile unsigned*)&g_sense == s) __nanosleep(64);
        }
        __threadfence();
    }
    __syncthreads();
}

__global__ __launch_bounds__(256) void stage3_kernel(const float* __restrict__ inp,
                                                     const float* __restrict__ mem,
                                                     const float* __restrict__ D2,
                                                     const float* __restrict__ CK,
                                                     const float* __restrict__ REC,
                                                     const int* __restrict__ xp,
                                                     const int* __restrict__ yp,
                                                     float* __restrict__ out) {
    __shared__ float a[8];
    __shared__ float w64[64];
    __shared__ float q[256];
    __shared__ float redsm[256];
    __shared__ float ratio_s;
    int b = blockIdx.x, j = threadIdx.x;
    int pix = xp[0] * 64 + yp[0];

    // ---- P1: rt (16 blocks), st (16), qt-inputs-part (16)
    if (b < 16) {
        if (j < 8) a[j] = __ldcg(&g_r128[b * 8 + j]);
        __syncthreads();
        float acc = 0.f;
#pragma unroll
        for (int u = 0; u < 8; u++) acc += a[u] * D2[(b * 8 + u) * 256 + j];
        atomicAdd(&g_rt[j], acc);
    } else if (b < 32) {
        int k0 = (b - 16) * 8;
        if (j < 8) a[j] = inp[k0 + j];
        __syncthreads();
        float acc = 0.f;
#pragma unroll
        for (int u = 0; u < 8; u++) acc += a[u] * REC[(k0 + u) * 256 + j];
        atomicAdd(&g_st[j], acc);
    } else if (b < 48) {
        int k0 = (b - 32) * 8;
        if (j < 8) a[j] = inp[k0 + j];
        __syncthreads();
        float acc = 0.f;
#pragma unroll
        for (int u = 0; u < 8; u++) acc += a[u] * CK[(k0 + u) * 256 + j];
        atomicAdd(&g_qt[j], acc);
    }
    gbar();

    // ---- P2: qt rt-part (32 blocks), d = (mem_t - st) @ write_update (32)
    if (b < 32) {
        int k0 = b * 8;
        if (j < 8) a[j] = __ldcg(&g_rt[k0 + j]);
        __syncthreads();
        float acc = 0.f;
#pragma unroll
        for (int u = 0; u < 8; u++) acc += a[u] * CK[(128 + k0 + u) * 256 + j];
        atomicAdd(&g_qt[j], acc);
    } else {
        int c0 = (b - 32) * 8;
        if (j < 8) a[j] = mem[pix * 256 + c0 + j] - __ldcg(&g_st[c0 + j]);
        __syncthreads();
        float acc = 0.f;
#pragma unroll
        for (int u = 0; u < 8; u++) acc += a[u] * REC[(128 + c0 + u) * 256 + j];
        atomicAdd(&g_d[j], acc);
    }
    gbar();

    // ---- P3: scores (64 px per block)
    q[j] = __ldcg(&g_qt[j]);
    __syncthreads();
    {
        int warp = j >> 5, lane = j & 31;
#pragma unroll
        for (int u = 0; u < 8; u++) {
            int p = b * 64 + warp * 8 + u;
            float acc = 0.f;
#pragma unroll
            for (int t = 0; t < 8; t++) acc += q[lane + 32 * t] * mem[p * 256 + lane + 32 * t];
#pragma unroll
            for (int off = 16; off; off >>= 1) acc += __shfl_down_sync(0xFFFFFFFFu, acc, off);
            if (lane == 0) g_scores[p] = acc;
        }
    }
    gbar();

    // ---- P4: softmax stats (block 0)
    if (b == 0) {
        float mx = -1e30f;
        for (int p = j; p < 4096; p += 256) mx = fmaxf(mx, __ldcg(&g_scores[p]));
        redsm[j] = mx;
        __syncthreads();
        for (int s = 128; s; s >>= 1) { if (j < s) redsm[j] = fmaxf(redsm[j], redsm[j + s]); __syncthreads(); }
        mx = redsm[0];
        __syncthreads();
        float sum = 0.f;
        for (int p = j; p < 4096; p += 256) sum += expf(__ldcg(&g_scores[p]) - mx);
        redsm[j] = sum;
        __syncthreads();
        for (int s = 128; s; s >>= 1) { if (j < s) redsm[j] += redsm[j + s]; __syncthreads(); }
        if (j == 0) { g_smax[0] = mx; g_smax[1] = redsm[0]; }
    }
    gbar();

    // ---- P5: ct partials (64 px per block)
    {
        float mx = __ldcg(&g_smax[0]);
        float inv = 1.0f / __ldcg(&g_smax[1]);
        if (j < 64) w64[j] = expf(__ldcg(&g_scores[b * 64 + j]) - mx) * inv;
        __syncthreads();
        float acc = 0.f;
#pragma unroll 4
        for (int u = 0; u < 64; u++) acc += w64[u] * mem[(b * 64 + u) * 256 + j];
        atomicAdd(&g_ct[j], acc);
    }
    gbar();

    // ---- P6: epilogue (block 0)
    if (b == 0) {
        float st = __ldcg(&g_st[j]), ct = __ldcg(&g_ct[j]), rt = __ldcg(&g_rt[j]);
        redsm[j] = st * ct;
        __syncthreads();
        for (int s = 128; s; s >>= 1) { if (j < s) redsm[j] += redsm[j + s]; __syncthreads(); }
        float local_imp = redsm[0];
        __syncthreads();
        redsm[j] = st * rt;
        __syncthreads();
        for (int s = 128; s; s >>= 1) { if (j < s) redsm[j] += redsm[j + s]; __syncthreads(); }
        if (j == 0) ratio_s = local_imp / (local_imp + redsm[0]);
        __syncthreads();
        out[j] = ct;
        out[256 + j] = rt;
        out[512 + (long)j * 4096 + pix] = mem[pix * 256 + j] + ratio_s * __ldcg(&g_d[j]);
    }
}

// ---------------- launch ----------------
extern "C" void kernel_launch(void* const* d_in, const int* in_sizes, int n_in,
                              void* d_out, int out_size) {
    const float* inputs = (const float*)d_in[0];
    const float* memory = (const float*)d_in[1];
    const float* K1     = (const float*)d_in[2];
    const float* K2     = (const float*)d_in[3];
    const float* D1     = (const float*)d_in[4];
    const float* D2     = (const float*)d_in[5];
    const float* CK     = (const float*)d_in[6];
    const float* REC    = (const float*)d_in[7];
    const int*   xp     = (const int*)d_in[8];
    const int*   yp     = (const int*)d_in[9];
    float* out = (float*)d_out;

    static int smem_set = 0;
    if (!smem_set) {
        cudaFuncSetAttribute(stage2_kernel, cudaFuncAttributeMaxDynamicSharedMemorySize,
                             20608 * 4);
        smem_set = 1;
    }

    stage1_kernel<<<704, 256>>>(memory, K1, D1, out);
    stage2_kernel<<<dim3(61, 2), 256, 20608 * 4>>>(K2, D1);
    stage3_kernel<<<64, 256>>>(inputs, memory, D2, CK, REC, xp, yp, out);
}

// round 9
// speedup vs baseline: 1.3091x; 1.3091x over previous
#include <cuda_runtime.h>
#include <cuda_bf16.h>

#define NFLAT 238144        // 64*61*61

// ---------------- scratch (device globals; no allocation) ----------------
__device__ __align__(128) float g_out1p[4 * 4096 * 32];
__device__ __align__(128) float g_pool[NFLAT];
__device__ __align__(128) float g_r128[128];
__device__ __align__(128) float g_rt[256];
__device__ __align__(128) float g_qt[256];
__device__ __align__(128) float g_st[256];
__device__ __align__(128) float g_d[256];
__device__ __align__(128) float g_ct[256];
__device__ __align__(128) float g_scores[4096];
__device__ __align__(128) float g_smax[32];
__device__ __align__(128) unsigned g_count;
__device__ __align__(128) unsigned g_sense;

// ---------------- packed fp32x2 helpers ----------------
typedef unsigned long long ull;
__device__ __forceinline__ ull pack2(float lo, float hi) {
    ull r; asm("mov.b64 %0, {%1,%2};" : "=l"(r) : "f"(lo), "f"(hi)); return r;
}
__device__ __forceinline__ void unpack2(ull v, float& lo, float& hi) {
    asm("mov.b64 {%0,%1}, %2;" : "=f"(lo), "=f"(hi) : "l"(v));
}
__device__ __forceinline__ void fma2(ull& d, ull a, ull b) {
    asm("fma.rn.f32x2 %0, %1, %2, %0;" : "+l"(d) : "l"(a), "l"(b));
}

// =========================================================================
// conv1: SAME 3x3, 256->32. 128 blocks: 2 rows x 64 ic each. 4px x 4oc/thread.
// =========================================================================
__global__ __launch_bounds__(256) void conv1_kernel(const float* __restrict__ mem,
                                                    const float* __restrict__ K1) {
    __shared__ float sIn[4288];     // 2 halves x 32ic x 67
    __shared__ float sW[3072];      // 3kw x 32ic x 32oc
    int bid = blockIdx.x;
    int tid = threadIdx.x;
    int icq  = bid & 3;
    int h0   = (bid >> 2) * 2;
    int half = tid >> 7;
    int t    = tid & 127;
    int pg = t & 15, og = t >> 4;

    ull acc0[4] = {0ull,0ull,0ull,0ull};
    ull acc1[4] = {0ull,0ull,0ull,0ull};

    for (int kh = 0; kh < 3; kh++) {
        for (int ch = 0; ch < 2; ch++) {
            int ic0 = icq * 64 + ch * 32;
            __syncthreads();
            for (int t2 = tid; t2 < 4224; t2 += 256) {
                int hh = (t2 >= 2112) ? 1 : 0;
                int lc = t2 - hh * 2112;
                int ic = lc & 31, c = lc >> 5;
                int r = h0 + kh - 1 + hh;
                int col = c - 1;
                float v = 0.f;
                if (r >= 0 && r < 64 && col >= 0 && col < 64)
                    v = mem[(r * 64 + col) * 256 + ic0 + ic];
                sIn[hh * 2144 + ic * 67 + c] = v;
            }
            for (int t2 = tid; t2 < 3072; t2 += 256) {
                int oc = t2 & 31, ic = (t2 >> 5) & 31, kw = t2 >> 10;
                sW[t2] = K1[((kh * 3 + kw) * 256 + ic0 + ic) * 32 + oc];
            }
            __syncthreads();
            const float* base = sIn + half * 2144;
#pragma unroll 4
            for (int ic = 0; ic < 32; ic++) {
                ull xb[6];
#pragma unroll
                for (int c = 0; c < 6; c++) {
                    float x = base[ic * 67 + pg * 4 + c];
                    xb[c] = pack2(x, x);
                }
#pragma unroll
                for (int kw = 0; kw < 3; kw++) {
                    const ull* wp = (const ull*)&sW[(kw * 32 + ic) * 32 + og * 4];
                    ull w0 = wp[0], w1 = wp[1];
#pragma unroll
                    for (int a = 0; a < 4; a++) {
                        fma2(acc0[a], xb[a + kw], w0);
                        fma2(acc1[a], xb[a + kw], w1);
                    }
                }
            }
        }
    }
    int row = h0 + half;
#pragma unroll
    for (int a = 0; a < 4; a++) {
        float l0, h1, l2, h3;
        unpack2(acc0[a], l0, h1);
        unpack2(acc1[a], l2, h3);
        *(float4*)&g_out1p[icq * 131072 + (row * 64 + pg * 4 + a) * 32 + og * 4] =
            make_float4(l0, h1, l2, h3);
    }
}

// =========================================================================
// conv2 + 2x2 mean-pool -> g_pool. grid (61, 2). Block (0,0) zeroes accumulators.
// =========================================================================
__global__ __launch_bounds__(256) void conv2_kernel(const float* __restrict__ K2) {
    extern __shared__ float sm2[];
    float* sIn = sm2;            // 4 rows x 32ic x 65 = 8320 (reused as sC[2][32][64])
    float* sW  = sm2 + 8320;     // 9*32*32 = 9216

    int i    = blockIdx.x;       // pooled row 0..60
    int half = blockIdx.y;
    int tid  = threadIdx.x;
    if (i == 0 && half == 0) {
        if (tid < 128) g_r128[tid] = 0.f;
        g_rt[tid] = 0.f; g_qt[tid] = 0.f; g_st[tid] = 0.f;
        g_d[tid] = 0.f;  g_ct[tid] = 0.f;
    }

    for (int t = tid; t < 8192; t += 256) {
        int ic = t & 31, col = (t >> 5) & 63, rr = t >> 11;
        const float* p = g_out1p + ((i + rr) * 64 + col) * 32 + ic;
        sIn[(rr * 32 + ic) * 65 + col] = p[0] + p[131072] + p[262144] + p[393216];
    }
    for (int t = tid; t < 9216; t += 256) {
        int ocl = t & 31, ic = (t >> 5) & 31, kk = t >> 10;
        sW[t] = K2[(kk * 32 + ic) * 64 + half * 32 + ocl];
    }
    __syncthreads();

    int pxg = tid & 31, ocg = tid >> 5;
    ull acc[2][2][2];
#pragma unroll
    for (int r = 0; r < 2; r++)
#pragma unroll
        for (int a = 0; a < 2; a++)
#pragma unroll
            for (int b = 0; b < 2; b++) acc[r][a][b] = 0ull;

    int px = pxg * 2;
    if (pxg < 31) {
#pragma unroll
        for (int r = 0; r < 2; r++)
            for (int kh = 0; kh < 3; kh++) {
#pragma unroll 4
                for (int ic = 0; ic < 32; ic++) {
                    ull xb[4];
#pragma unroll
                    for (int c = 0; c < 4; c++) {
                        float x = sIn[((r + kh) * 32 + ic) * 65 + px + c];
                        xb[c] = pack2(x, x);
                    }
#pragma unroll
                    for (int kw = 0; kw < 3; kw++) {
                        const ull* wp = (const ull*)&sW[((kh * 3 + kw) * 32 + ic) * 32 + ocg * 4];
                        ull w0 = wp[0], w1 = wp[1];
                        fma2(acc[r][0][0], xb[kw + 0], w0);
                        fma2(acc[r][0][1], xb[kw + 0], w1);
                        fma2(acc[r][1][0], xb[kw + 1], w0);
                        fma2(acc[r][1][1], xb[kw + 1], w1);
                    }
                }
            }
    }
    __syncthreads();
    if (pxg < 31) {
#pragma unroll
        for (int r = 0; r < 2; r++)
#pragma unroll
            for (int b = 0; b < 2; b++) {
                float lo, hi;
                unpack2(acc[r][0][b], lo, hi);
                sIn[(r * 32 + ocg * 4 + b * 2 + 0) * 64 + px + 0] = lo;
                sIn[(r * 32 + ocg * 4 + b * 2 + 1) * 64 + px + 0] = hi;
                unpack2(acc[r][1][b], lo, hi);
                sIn[(r * 32 + ocg * 4 + b * 2 + 0) * 64 + px + 1] = lo;
                sIn[(r * 32 + ocg * 4 + b * 2 + 1) * 64 + px + 1] = hi;
            }
    }
    __syncthreads();
    // pool and write to g_pool flat layout: f = oc*3721 + i*61 + j
    for (int t = tid; t < 2048; t += 256) {
        int j = t & 63, ocl = t >> 6;
        if (j < 61) {
            float v = 0.25f * (sIn[ocl * 64 + j] + sIn[ocl * 64 + j + 1] +
                               sIn[(32 + ocl) * 64 + j] + sIn[(32 + ocl) * 64 + j + 1]);
            g_pool[(half * 32 + ocl) * 3721 + i * 61 + j] = v;
        }
    }
}

// =========================================================================
// GEMV (466 blocks) + transpose (256 blocks) in one launch
// =========================================================================
__global__ __launch_bounds__(256) void gemvtrans_kernel(const float* __restrict__ D1,
                                                        const float* __restrict__ mem,
                                                        float* __restrict__ out) {
    __shared__ float sm[4224];   // transpose tile 128x33; gemv uses [0:512) + red[1024)
    int bid = blockIdx.x;
    int tid = threadIdx.x;

    if (bid < 466) {
        float* sp  = sm;         // 512 pooled values
        float* red = sm + 512;   // 8 x 128
        int fbase = bid * 512;
        int n = NFLAT - fbase; if (n > 512) n = 512;
        for (int t = tid; t < 512; t += 256) sp[t] = (t < n) ? g_pool[fbase + t] : 0.f;
        __syncthreads();
        int kq = tid & 31, slot = tid >> 5;
        const float4* D1v = (const float4*)D1;
        float4 a4 = make_float4(0.f, 0.f, 0.f, 0.f);
        int rr = slot;
        for (; rr + 24 < n; rr += 32) {
            float s0 = sp[rr], s1 = sp[rr + 8], s2 = sp[rr + 16], s3 = sp[rr + 24];
            float4 d0 = D1v[(long)(fbase + rr)      * 32 + kq];
            float4 d1 = D1v[(long)(fbase + rr + 8)  * 32 + kq];
            float4 d2 = D1v[(long)(fbase + rr + 16) * 32 + kq];
            float4 d3 = D1v[(long)(fbase + rr + 24) * 32 + kq];
            a4.x += s0 * d0.x + s1 * d1.x + s2 * d2.x + s3 * d3.x;
            a4.y += s0 * d0.y + s1 * d1.y + s2 * d2.y + s3 * d3.y;
            a4.z += s0 * d0.z + s1 * d1.z + s2 * d2.z + s3 * d3.z;
            a4.w += s0 * d0.w + s1 * d1.w + s2 * d2.w + s3 * d3.w;
        }
        for (; rr < n; rr += 8) {
            float s = sp[rr];
            float4 dv = D1v[(long)(fbase + rr) * 32 + kq];
            a4.x += s * dv.x; a4.y += s * dv.y; a4.z += s * dv.z; a4.w += s * dv.w;
        }
        float* rp = &red[slot * 128 + kq * 4];
        rp[0] = a4.x; rp[1] = a4.y; rp[2] = a4.z; rp[3] = a4.w;
        __syncthreads();
        if (tid < 128) {
            float v = 0.f;
#pragma unroll
            for (int s = 0; s < 8; s++) v += red[s * 128 + tid];
            atomicAdd(&g_r128[tid], v);
        }
    } else {
        // transpose memory -> out[512 + c*4096 + p], 128p x 32c tiles
        int tb = bid - 466;
        float* tile = sm;   // 128 x 33
        int p0 = (tb >> 3) * 128;
        int c0 = (tb & 7) * 32;
        for (int t2 = tid; t2 < 4096; t2 += 256) {
            int p = t2 >> 5, c = t2 & 31;
            tile[p * 33 + c] = mem[(p0 + p) * 256 + c0 + c];
        }
        __syncthreads();
        for (int t2 = tid; t2 < 4096; t2 += 256) {
            int c = t2 >> 7, p = t2 & 127;
            out[512 + (long)(c0 + c) * 4096 + p0 + p] = tile[p * 33 + c];
        }
    }
}

// =========================================================================
// STAGE 3: persistent tail chain, 64 blocks, sense-reversal grid barrier
// =========================================================================
__device__ __forceinline__ void gbar() {
    __syncthreads();
    if (threadIdx.x == 0) {
        __threadfence();
        unsigned s = *(volatile unsigned*)&g_sense;
        unsigned prev = atomicAdd(&g_count, 1u);
        if (prev == 63u) {
            g_count = 0u;              // reset BEFORE releasing
            __threadfence();
            atomicExch(&g_sense, s + 1u);
        } else {
            while (*(volatile unsigned*)&g_sense == s) __nanosleep(64);
        }
        __threadfence();
    }
    __syncthreads();
}

__global__ __launch_bounds__(256) void stage3_kernel(const float* __restrict__ inp,
                                                     const float* __restrict__ mem,
                                                     const float* __restrict__ D2,
                                                     const float* __restrict__ CK,
                                                     const float* __restrict__ REC,
                                                     const int* __restrict__ xp,
                                                     const int* __restrict__ yp,
                                                     float* __restrict__ out) {
    __shared__ float a[8];
    __shared__ float w64[64];
    __shared__ float q[256];
    __shared__ float redsm[256];
    __shared__ float ratio_s;
    int b = blockIdx.x, j = threadIdx.x;
    int pix = xp[0] * 64 + yp[0];

    // ---- P1: rt (16 blocks), st (16), qt-inputs-part (16)
    if (b < 16) {
        if (j < 8) a[j] = __ldcg(&g_r128[b * 8 + j]);
        __syncthreads();
        float acc = 0.f;
#pragma unroll
        for (int u = 0; u < 8; u++) acc += a[u] * D2[(b * 8 + u) * 256 + j];
        atomicAdd(&g_rt[j], acc);
    } else if (b < 32) {
        int k0 = (b - 16) * 8;
        if (j < 8) a[j] = inp[k0 + j];
        __syncthreads();
        float acc = 0.f;
#pragma unroll
        for (int u = 0; u < 8; u++) acc += a[u] * REC[(k0 + u) * 256 + j];
        atomicAdd(&g_st[j], acc);
    } else if (b < 48) {
        int k0 = (b - 32) * 8;
        if (j < 8) a[j] = inp[k0 + j];
        __syncthreads();
        float acc = 0.f;
#pragma unroll
        for (int u = 0; u < 8; u++) acc += a[u] * CK[(k0 + u) * 256 + j];
        atomicAdd(&g_qt[j], acc);
    }
    gbar();

    // ---- P2: qt rt-part (32 blocks), d = (mem_t - st) @ write_update (32)
    if (b < 32) {
        int k0 = b * 8;
        if (j < 8) a[j] = __ldcg(&g_rt[k0 + j]);
        __syncthreads();
        float acc = 0.f;
#pragma unroll
        for (int u = 0; u < 8; u++) acc += a[u] * CK[(128 + k0 + u) * 256 + j];
        atomicAdd(&g_qt[j], acc);
    } else {
        int c0 = (b - 32) * 8;
        if (j < 8) a[j] = mem[pix * 256 + c0 + j] - __ldcg(&g_st[c0 + j]);
        __syncthreads();
        float acc = 0.f;
#pragma unroll
        for (int u = 0; u < 8; u++) acc += a[u] * REC[(128 + c0 + u) * 256 + j];
        atomicAdd(&g_d[j], acc);
    }
    gbar();

    // ---- P3: scores (64 px per block)
    q[j] = __ldcg(&g_qt[j]);
    __syncthreads();
    {
        int warp = j >> 5, lane = j & 31;
#pragma unroll
        for (int u = 0; u < 8; u++) {
            int p = b * 64 + warp * 8 + u;
            float acc = 0.f;
#pragma unroll
            for (int t = 0; t < 8; t++) acc += q[lane + 32 * t] * mem[p * 256 + lane + 32 * t];
#pragma unroll
            for (int off = 16; off; off >>= 1) acc += __shfl_down_sync(0xFFFFFFFFu, acc, off);
            if (lane == 0) g_scores[p] = acc;
        }
    }
    gbar();

    // ---- P4: softmax stats (block 0)
    if (b == 0) {
        float mx = -1e30f;
        for (int p = j; p < 4096; p += 256) mx = fmaxf(mx, __ldcg(&g_scores[p]));
        redsm[j] = mx;
        __syncthreads();
        for (int s = 128; s; s >>= 1) { if (j < s) redsm[j] = fmaxf(redsm[j], redsm[j + s]); __syncthreads(); }
        mx = redsm[0];
        __syncthreads();
        float sum = 0.f;
        for (int p = j; p < 4096; p += 256) sum += expf(__ldcg(&g_scores[p]) - mx);
        redsm[j] = sum;
        __syncthreads();
        for (int s = 128; s; s >>= 1) { if (j < s) redsm[j] += redsm[j + s]; __syncthreads(); }
        if (j == 0) { g_smax[0] = mx; g_smax[1] = redsm[0]; }
    }
    gbar();

    // ---- P5: ct partials (64 px per block)
    {
        float mx = __ldcg(&g_smax[0]);
        float inv = 1.0f / __ldcg(&g_smax[1]);
        if (j < 64) w64[j] = expf(__ldcg(&g_scores[b * 64 + j]) - mx) * inv;
        __syncthreads();
        float acc = 0.f;
#pragma unroll 4
        for (int u = 0; u < 64; u++) acc += w64[u] * mem[(b * 64 + u) * 256 + j];
        atomicAdd(&g_ct[j], acc);
    }
    gbar();

    // ---- P6: epilogue (block 0)
    if (b == 0) {
        float st = __ldcg(&g_st[j]), ct = __ldcg(&g_ct[j]), rt = __ldcg(&g_rt[j]);
        redsm[j] = st * ct;
        __syncthreads();
        for (int s = 128; s; s >>= 1) { if (j < s) redsm[j] += redsm[j + s]; __syncthreads(); }
        float local_imp = redsm[0];
        __syncthreads();
        redsm[j] = st * rt;
        __syncthreads();
        for (int s = 128; s; s >>= 1) { if (j < s) redsm[j] += redsm[j + s]; __syncthreads(); }
        if (j == 0) ratio_s = local_imp / (local_imp + redsm[0]);
        __syncthreads();
        out[j] = ct;
        out[256 + j] = rt;
        out[512 + (long)j * 4096 + pix] = mem[pix * 256 + j] + ratio_s * __ldcg(&g_d[j]);
    }
}

// ---------------- launch ----------------
extern "C" void kernel_launch(void* const* d_in, const int* in_sizes, int n_in,
                              void* d_out, int out_size) {
    const float* inputs = (const float*)d_in[0];
    const float* memory = (const float*)d_in[1];
    const float* K1     = (const float*)d_in[2];
    const float* K2     = (const float*)d_in[3];
    const float* D1     = (const float*)d_in[4];
    const float* D2     = (const float*)d_in[5];
    const float* CK     = (const float*)d_in[6];
    const float* REC    = (const float*)d_in[7];
    const int*   xp     = (const int*)d_in[8];
    const int*   yp     = (const int*)d_in[9];
    float* out = (float*)d_out;

    static int smem_set = 0;
    if (!smem_set) {
        cudaFuncSetAttribute(conv2_kernel, cudaFuncAttributeMaxDynamicSharedMemorySize,
                             17536 * 4);
        smem_set = 1;
    }

    conv1_kernel<<<128, 256>>>(memory, K1);
    conv2_kernel<<<dim3(61, 2), 256, 17536 * 4>>>(K2);
    gemvtrans_kernel<<<722, 256>>>(D1, memory, out);
    stage3_kernel<<<64, 256>>>(inputs, memory, D2, CK, REC, xp, yp, out);
}

// round 12
// speedup vs baseline: 1.3645x; 1.0423x over previous
#include <cuda_runtime.h>
#include <cuda_bf16.h>

#define NFLAT 238144        // 64*61*61

// ---------------- scratch (device globals; no allocation) ----------------
__device__ __align__(128) float g_out1p[4 * 4096 * 32];
__device__ __align__(128) float g_pool[NFLAT];
__device__ __align__(128) float g_r128[128];
__device__ __align__(128) float g_rt[256];
__device__ __align__(128) float g_qt[256];
__device__ __align__(128) float g_st[256];
__device__ __align__(128) float g_d[256];
__device__ __align__(128) float g_ct[256];
__device__ __align__(128) float g_scores[4096];
__device__ __align__(128) float g_sinkv[128];
__device__ __align__(128) unsigned g_maxu;
__device__ __align__(128) float g_sumexp;
__device__ __align__(128) unsigned g_count;
__device__ __align__(128) unsigned g_sense;

// ---------------- packed fp32x2 helpers ----------------
typedef unsigned long long ull;
__device__ __forceinline__ ull pack2(float lo, float hi) {
    ull r; asm("mov.b64 %0, {%1,%2};" : "=l"(r) : "f"(lo), "f"(hi)); return r;
}
__device__ __forceinline__ void unpack2(ull v, float& lo, float& hi) {
    asm("mov.b64 {%0,%1}, %2;" : "=f"(lo), "=f"(hi) : "l"(v));
}
__device__ __forceinline__ void fma2(ull& d, ull a, ull b) {
    asm("fma.rn.f32x2 %0, %1, %2, %0;" : "+l"(d) : "l"(a), "l"(b));
}

// ---------------- ordered-uint float encode (for atomicMax) ----------------
__device__ __forceinline__ unsigned enc_f(float f) {
    unsigned b = __float_as_uint(f);
    return (b & 0x80000000u) ? ~b : (b | 0x80000000u);
}
__device__ __forceinline__ float dec_f(unsigned u) {
    return (u & 0x80000000u) ? __uint_as_float(u & 0x7FFFFFFFu) : __uint_as_float(~u);
}

// =========================================================================
// conv1 (128 blocks) + transpose->out (256 blocks)
// =========================================================================
__global__ __launch_bounds__(256) void conv1trans_kernel(const float* __restrict__ mem,
                                                         const float* __restrict__ K1,
                                                         float* __restrict__ out) {
    __shared__ float sm[7360];
    int bid = blockIdx.x;
    int tid = threadIdx.x;

    if (bid < 128) {
        float* sIn = sm;            // 2 halves x 32ic x 67 = 4288
        float* sW  = sm + 4288;     // 3kw x 32ic x 32oc = 3072
        int icq  = bid & 3;
        int h0   = (bid >> 2) * 2;
        int half = tid >> 7;
        int t    = tid & 127;
        int pg = t & 15, og = t >> 4;

        ull acc0[4] = {0ull,0ull,0ull,0ull};
        ull acc1[4] = {0ull,0ull,0ull,0ull};

        for (int kh = 0; kh < 3; kh++) {
            for (int ch = 0; ch < 2; ch++) {
                int ic0 = icq * 64 + ch * 32;
                __syncthreads();
                for (int t2 = tid; t2 < 4224; t2 += 256) {
                    int hh = (t2 >= 2112) ? 1 : 0;
                    int lc = t2 - hh * 2112;
                    int ic = lc & 31, c = lc >> 5;
                    int r = h0 + kh - 1 + hh;
                    int col = c - 1;
                    float v = 0.f;
                    if (r >= 0 && r < 64 && col >= 0 && col < 64)
                        v = mem[(r * 64 + col) * 256 + ic0 + ic];
                    sIn[hh * 2144 + ic * 67 + c] = v;
                }
                for (int t2 = tid; t2 < 3072; t2 += 256) {
                    int oc = t2 & 31, ic = (t2 >> 5) & 31, kw = t2 >> 10;
                    sW[t2] = K1[((kh * 3 + kw) * 256 + ic0 + ic) * 32 + oc];
                }
                __syncthreads();
                const float* base = sIn + half * 2144;
#pragma unroll 4
                for (int ic = 0; ic < 32; ic++) {
                    ull xb[6];
#pragma unroll
                    for (int c = 0; c < 6; c++) {
                        float x = base[ic * 67 + pg * 4 + c];
                        xb[c] = pack2(x, x);
                    }
#pragma unroll
                    for (int kw = 0; kw < 3; kw++) {
                        const ull* wp = (const ull*)&sW[(kw * 32 + ic) * 32 + og * 4];
                        ull w0 = wp[0], w1 = wp[1];
#pragma unroll
                        for (int a = 0; a < 4; a++) {
                            fma2(acc0[a], xb[a + kw], w0);
                            fma2(acc1[a], xb[a + kw], w1);
                        }
                    }
                }
            }
        }
        int row = h0 + half;
#pragma unroll
        for (int a = 0; a < 4; a++) {
            float l0, h1, l2, h3;
            unpack2(acc0[a], l0, h1);
            unpack2(acc1[a], l2, h3);
            *(float4*)&g_out1p[icq * 131072 + (row * 64 + pg * 4 + a) * 32 + og * 4] =
                make_float4(l0, h1, l2, h3);
        }
    } else {
        // transpose memory -> out[512 + c*4096 + p], 128p x 32c tiles
        int tb = bid - 128;
        float* tile = sm;   // 128 x 33 = 4224
        int p0 = (tb >> 3) * 128;
        int c0 = (tb & 7) * 32;
        for (int t2 = tid; t2 < 4096; t2 += 256) {
            int p = t2 >> 5, c = t2 & 31;
            tile[p * 33 + c] = mem[(p0 + p) * 256 + c0 + c];
        }
        __syncthreads();
        for (int t2 = tid; t2 < 4096; t2 += 256) {
            int c = t2 >> 7, p = t2 & 127;
            out[512 + (long)(c0 + c) * 4096 + p0 + p] = tile[p * 33 + c];
        }
    }
}

// =========================================================================
// conv2 + 2x2 mean-pool -> g_pool. grid (61, 2). Block (0,0) zeroes accumulators.
// =========================================================================
__global__ __launch_bounds__(256) void conv2_kernel(const float* __restrict__ K2) {
    extern __shared__ float sm2[];
    float* sIn = sm2;            // 4 rows x 32ic x 65 = 8320 (reused as sC[2][32][64])
    float* sW  = sm2 + 8320;     // 9*32*32 = 9216

    int i    = blockIdx.x;
    int half = blockIdx.y;
    int tid  = threadIdx.x;
    if (i == 0 && half == 0) {
        if (tid < 128) g_r128[tid] = 0.f;
        g_rt[tid] = 0.f; g_qt[tid] = 0.f; g_st[tid] = 0.f;
        g_d[tid] = 0.f;  g_ct[tid] = 0.f;
        if (tid == 0) { g_maxu = 0u; g_sumexp = 0.f; }
    }

    for (int t = tid; t < 8192; t += 256) {
        int ic = t & 31, col = (t >> 5) & 63, rr = t >> 11;
        const float* p = g_out1p + ((i + rr) * 64 + col) * 32 + ic;
        sIn[(rr * 32 + ic) * 65 + col] = p[0] + p[131072] + p[262144] + p[393216];
    }
    for (int t = tid; t < 9216; t += 256) {
        int ocl = t & 31, ic = (t >> 5) & 31, kk = t >> 10;
        sW[t] = K2[(kk * 32 + ic) * 64 + half * 32 + ocl];
    }
    __syncthreads();

    int pxg = tid & 31, ocg = tid >> 5;
    ull acc[2][2][2];
#pragma unroll
    for (int r = 0; r < 2; r++)
#pragma unroll
        for (int a = 0; a < 2; a++)
#pragma unroll
            for (int b = 0; b < 2; b++) acc[r][a][b] = 0ull;

    int px = pxg * 2;
    if (pxg < 31) {
#pragma unroll
        for (int r = 0; r < 2; r++)
            for (int kh = 0; kh < 3; kh++) {
#pragma unroll 4
                for (int ic = 0; ic < 32; ic++) {
                    ull xb[4];
#pragma unroll
                    for (int c = 0; c < 4; c++) {
                        float x = sIn[((r + kh) * 32 + ic) * 65 + px + c];
                        xb[c] = pack2(x, x);
                    }
#pragma unroll
                    for (int kw = 0; kw < 3; kw++) {
                        const ull* wp = (const ull*)&sW[((kh * 3 + kw) * 32 + ic) * 32 + ocg * 4];
                        ull w0 = wp[0], w1 = wp[1];
                        fma2(acc[r][0][0], xb[kw + 0], w0);
                        fma2(acc[r][0][1], xb[kw + 0], w1);
                        fma2(acc[r][1][0], xb[kw + 1], w0);
                        fma2(acc[r][1][1], xb[kw + 1], w1);
                    }
                }
            }
    }
    __syncthreads();
    if (pxg < 31) {
#pragma unroll
        for (int r = 0; r < 2; r++)
#pragma unroll
            for (int b = 0; b < 2; b++) {
                float lo, hi;
                unpack2(acc[r][0][b], lo, hi);
                sIn[(r * 32 + ocg * 4 + b * 2 + 0) * 64 + px + 0] = lo;
                sIn[(r * 32 + ocg * 4 + b * 2 + 1) * 64 + px + 0] = hi;
                unpack2(acc[r][1][b], lo, hi);
                sIn[(r * 32 + ocg * 4 + b * 2 + 0) * 64 + px + 1] = lo;
                sIn[(r * 32 + ocg * 4 + b * 2 + 1) * 64 + px + 1] = hi;
            }
    }
    __syncthreads();
    for (int t = tid; t < 2048; t += 256) {
        int j = t & 63, ocl = t >> 6;
        if (j < 61) {
            float v = 0.25f * (sIn[ocl * 64 + j] + sIn[ocl * 64 + j + 1] +
                               sIn[(32 + ocl) * 64 + j] + sIn[(32 + ocl) * 64 + j + 1]);
            g_pool[(half * 32 + ocl) * 3721 + i * 61 + j] = v;
        }
    }
}

// =========================================================================
// GEMV: r128 += pool @ D1. 466 blocks, 8-deep float4 unroll.
// =========================================================================
__global__ __launch_bounds__(256) void gemv_kernel(const float* __restrict__ D1) {
    __shared__ float sp[512];
    __shared__ float red[8 * 128];
    int fbase = blockIdx.x * 512;
    int n = NFLAT - fbase; if (n > 512) n = 512;
    for (int t = threadIdx.x; t < 512; t += 256) sp[t] = (t < n) ? g_pool[fbase + t] : 0.f;
    __syncthreads();
    int kq = threadIdx.x & 31, slot = threadIdx.x >> 5;
    const float4* D1v = (const float4*)D1;
    float4 a4 = make_float4(0.f, 0.f, 0.f, 0.f);
    int rr = slot;
    for (; rr + 56 < n; rr += 64) {
        float4 d[8];
        float s[8];
#pragma unroll
        for (int u = 0; u < 8; u++) {
            s[u] = sp[rr + u * 8];
            d[u] = D1v[(long)(fbase + rr + u * 8) * 32 + kq];
        }
#pragma unroll
        for (int u = 0; u < 8; u++) {
            a4.x += s[u] * d[u].x; a4.y += s[u] * d[u].y;
            a4.z += s[u] * d[u].z; a4.w += s[u] * d[u].w;
        }
    }
    for (; rr < n; rr += 8) {
        float s = sp[rr];
        float4 dv = D1v[(long)(fbase + rr) * 32 + kq];
        a4.x += s * dv.x; a4.y += s * dv.y; a4.z += s * dv.z; a4.w += s * dv.w;
    }
    float* rp = &red[slot * 128 + kq * 4];
    rp[0] = a4.x; rp[1] = a4.y; rp[2] = a4.z; rp[3] = a4.w;
    __syncthreads();
    if (threadIdx.x < 128) {
        float v = 0.f;
#pragma unroll
        for (int s = 0; s < 8; s++) v += red[s * 128 + threadIdx.x];
        atomicAdd(&g_r128[threadIdx.x], v);
    }
}

// =========================================================================
// STAGE 3: persistent tail chain, 128 blocks, 4 sense-reversal grid barriers
// =========================================================================
__device__ __forceinline__ void gbar() {
    __syncthreads();
    if (threadIdx.x == 0) {
        __threadfence();
        unsigned s = *(volatile unsigned*)&g_sense;
        unsigned prev = atomicAdd(&g_count, 1u);
        if (prev == 127u) {
            g_count = 0u;
            __threadfence();
            atomicExch(&g_sense, s + 1u);
        } else {
            while (*(volatile unsigned*)&g_sense == s) __nanosleep(32);
        }
        __threadfence();
    }
    __syncthreads();
}

__global__ __launch_bounds__(256) void stage3_kernel(const float* __restrict__ inp,
                                                     const float* __restrict__ mem,
                                                     const float* __restrict__ D2,
                                                     const float* __restrict__ CK,
                                                     const float* __restrict__ REC,
                                                     const int* __restrict__ xp,
                                                     const int* __restrict__ yp,
                                                     float* __restrict__ out) {
    __shared__ float a[8];
    __shared__ float qs[256];
    __shared__ float sc[32];
    __shared__ float w32[32];
    __shared__ float redsm[256];
    __shared__ float ratio_s;
    int b = blockIdx.x, j = threadIdx.x;
    int pix = xp[0] * 64 + yp[0];

    // ---- P1: rt (16), st (16), qt-input (16), mem->L2 prefetch (80)
    if (b < 16) {
        if (j < 8) a[j] = __ldcg(&g_r128[b * 8 + j]);
        __syncthreads();
        float acc = 0.f;
#pragma unroll
        for (int u = 0; u < 8; u++) acc += a[u] * D2[(b * 8 + u) * 256 + j];
        atomicAdd(&g_rt[j], acc);
    } else if (b < 32) {
        int k0 = (b - 16) * 8;
        if (j < 8) a[j] = inp[k0 + j];
        __syncthreads();
        float acc = 0.f;
#pragma unroll
        for (int u = 0; u < 8; u++) acc += a[u] * REC[(k0 + u) * 256 + j];
        atomicAdd(&g_st[j], acc);
    } else if (b < 48) {
        int k0 = (b - 32) * 8;
        if (j < 8) a[j] = inp[k0 + j];
        __syncthreads();
        float acc = 0.f;
#pragma unroll
        for (int u = 0; u < 8; u++) acc += a[u] * CK[(k0 + u) * 256 + j];
        atomicAdd(&g_qt[j], acc);
    } else {
        // prefetch mem (4MB) into L2 for P3/P5
        int pb = b - 48;                 // 0..79
        const float4* mv = (const float4*)mem;
        int start = pb * 3277;
        int end = start + 3277; if (end > 262144) end = 262144;
        float s = 0.f;
        for (int u = start + j; u < end; u += 256) {
            float4 v = __ldcg(&mv[u]);
            s += v.x + v.y + v.z + v.w;
        }
        g_sinkv[b] = s;
    }
    gbar();

    // ---- P2: qt rt-part (32), d = (mem_t - st) @ write_update (32)
    if (b < 32) {
        int k0 = b * 8;
        if (j < 8) a[j] = __ldcg(&g_rt[k0 + j]);
        __syncthreads();
        float acc = 0.f;
#pragma unroll
        for (int u = 0; u < 8; u++) acc += a[u] * CK[(128 + k0 + u) * 256 + j];
        atomicAdd(&g_qt[j], acc);
    } else if (b < 64) {
        int c0 = (b - 32) * 8;
        if (j < 8) a[j] = mem[pix * 256 + c0 + j] - __ldcg(&g_st[c0 + j]);
        __syncthreads();
        float acc = 0.f;
#pragma unroll
        for (int u = 0; u < 8; u++) acc += a[u] * REC[(128 + c0 + u) * 256 + j];
        atomicAdd(&g_d[j], acc);
    }
    gbar();

    // ---- P3: scores (32 px per block) + block max -> atomicMax
    qs[j] = __ldcg(&g_qt[j]);
    __syncthreads();
    {
        int warp = j >> 5, lane = j & 31;
        int pbase = b * 32 + warp * 4;
        // lane covers cols [lane*8, lane*8+8)
        float qa0 = qs[lane * 8 + 0], qa1 = qs[lane * 8 + 1], qa2 = qs[lane * 8 + 2], qa3 = qs[lane * 8 + 3];
        float qb0 = qs[lane * 8 + 4], qb1 = qs[lane * 8 + 5], qb2 = qs[lane * 8 + 6], qb3 = qs[lane * 8 + 7];
        const float4* mv = (const float4*)mem;
        float4 m0[4], m1[4];
#pragma unroll
        for (int u = 0; u < 4; u++) {
            long base = (long)(pbase + u) * 64 + lane * 2;
            m0[u] = mv[base];
            m1[u] = mv[base + 1];
        }
#pragma unroll
        for (int u = 0; u < 4; u++) {
            float acc = m0[u].x * qa0 + m0[u].y * qa1 + m0[u].z * qa2 + m0[u].w * qa3
                      + m1[u].x * qb0 + m1[u].y * qb1 + m1[u].z * qb2 + m1[u].w * qb3;
#pragma unroll
            for (int off = 16; off; off >>= 1) acc += __shfl_down_sync(0xFFFFFFFFu, acc, off);
            if (lane == 0) { g_scores[pbase + u] = acc; sc[warp * 4 + u] = acc; }
        }
    }
    __syncthreads();
    if (j < 32) {
        float v = sc[j];
#pragma unroll
        for (int off = 16; off; off >>= 1) v = fmaxf(v, __shfl_down_sync(0xFFFFFFFFu, v, off));
        if (j == 0) atomicMax(&g_maxu, enc_f(v));
    }
    gbar();

    // ---- P5: unnormalized ct partials (32 px per block) + sumexp
    {
        float mx = dec_f(*(volatile unsigned*)&g_maxu);
        int p0 = b * 32;
        if (j < 32) w32[j] = expf(__ldcg(&g_scores[p0 + j]) - mx);
        __syncthreads();
        if (j < 32) {
            float v = w32[j];
#pragma unroll
            for (int off = 16; off; off >>= 1) v += __shfl_down_sync(0xFFFFFFFFu, v, off);
            if (j == 0) atomicAdd(&g_sumexp, v);
        }
        float acc = 0.f;
#pragma unroll
        for (int u = 0; u < 32; u++) acc += w32[u] * mem[(p0 + u) * 256 + j];
        atomicAdd(&g_ct[j], acc);
    }
    gbar();

    // ---- P6: epilogue (block 0)
    if (b == 0) {
        float inv = 1.0f / *((volatile float*)&g_sumexp);
        float st = __ldcg(&g_st[j]);
        float ct = __ldcg(&g_ct[j]) * inv;
        float rt = __ldcg(&g_rt[j]);
        redsm[j] = st * ct;
        __syncthreads();
        for (int s = 128; s; s >>= 1) { if (j < s) redsm[j] += redsm[j + s]; __syncthreads(); }
        float local_imp = redsm[0];
        __syncthreads();
        redsm[j] = st * rt;
        __syncthreads();
        for (int s = 128; s; s >>= 1) { if (j < s) redsm[j] += redsm[j + s]; __syncthreads(); }
        if (j == 0) ratio_s = local_imp / (local_imp + redsm[0]);
        __syncthreads();
        out[j] = ct;
        out[256 + j] = rt;
        out[512 + (long)j * 4096 + pix] = mem[pix * 256 + j] + ratio_s * __ldcg(&g_d[j]);
    }
}

// ---------------- launch ----------------
extern "C" void kernel_launch(void* const* d_in, const int* in_sizes, int n_in,
                              void* d_out, int out_size) {
    const float* inputs = (const float*)d_in[0];
    const float* memory = (const float*)d_in[1];
    const float* K1     = (const float*)d_in[2];
    const float* K2     = (const float*)d_in[3];
    const float* D1     = (const float*)d_in[4];
    const float* D2     = (const float*)d_in[5];
    const float* CK     = (const float*)d_in[6];
    const float* REC    = (const float*)d_in[7];
    const int*   xp     = (const int*)d_in[8];
    const int*   yp     = (const int*)d_in[9];
    float* out = (float*)d_out;

    static int smem_set = 0;
    if (!smem_set) {
        cudaFuncSetAttribute(conv2_kernel, cudaFuncAttributeMaxDynamicSharedMemorySize,
                             17536 * 4);
        smem_set = 1;
    }

    conv1trans_kernel<<<384, 256>>>(memory, K1, out);
    conv2_kernel<<<dim3(61, 2), 256, 17536 * 4>>>(K2);
    gemv_kernel<<<466, 256>>>(D1);
    stage3_kernel<<<128, 256>>>(inputs, memory, D2, CK, REC, xp, yp, out);
}